// round 15
// baseline (speedup 1.0000x reference)
#include <cuda_runtime.h>
#include <cuda_fp16.h>
#include <cstdint>

#define NSEQ 2048
#define DH 64
#define NBH 32
#define MTILE 64
#define CHUNK 32
#define NCHUNK (NSEQ/CHUNK)     // 64  (pass 2)
#define P1CHUNK 64
#define NP1CHUNK (NSEQ/P1CHUNK) // 32  (pass 1)
#define NELEM (NBH*NSEQ*DH)     // 4194304

// preconverted fp16 operands (q pre-scaled by 1/8; all hi-only)
__device__ __align__(16) __half g_qhi[NELEM];
__device__ __align__(16) __half g_khi[NELEM];
__device__ __align__(16) __half g_vhi[NELEM];

// smem layout (144B row stride):
//   Qhi (64 rows, 9216B) | 2 x 9216B buffers
//   pass 1: each buffer = one 64-row Khi tile
//   pass 2: each buffer = [Khi|Vhi] 32-row tiles
#define SM_QHI 0
#define SM_BUF 9216
#define TILE_B (CHUNK*144)      // 4608
#define BUF_B  (2*TILE_B)       // 9216
#define SMEM_TOTAL (SM_BUF + 2*BUF_B)   // 27648 -> 4 CTAs/SM (reg-capped)

#define CP16(d,s)   asm volatile("cp.async.cg.shared.global [%0], [%1], 16;"::"r"(d),"l"(s))
#define CP_COMMIT() asm volatile("cp.async.commit_group;")
#define CP_WAIT1()  asm volatile("cp.async.wait_group 1;")
#define LDSM4(r0,r1,r2,r3,a)  asm volatile("ldmatrix.sync.aligned.m8n8.x4.shared.b16 {%0,%1,%2,%3},[%4];":"=r"(r0),"=r"(r1),"=r"(r2),"=r"(r3):"r"(a))
#define LDSM4T(r0,r1,r2,r3,a) asm volatile("ldmatrix.sync.aligned.m8n8.x4.trans.shared.b16 {%0,%1,%2,%3},[%4];":"=r"(r0),"=r"(r1),"=r"(r2),"=r"(r3):"r"(a))

static __device__ __forceinline__ uint32_t smem_u32(const void* p){
    uint32_t a; asm("{ .reg .u64 t; cvta.to.shared.u64 t, %1; cvt.u32.u64 %0, t; }":"=r"(a):"l"(p)); return a;
}
static __device__ __forceinline__ void mma_f16(float* d, const uint32_t* a, uint32_t b0, uint32_t b1){
    asm volatile("mma.sync.aligned.m16n8k16.row.col.f32.f16.f16.f32 "
        "{%0,%1,%2,%3},{%4,%5,%6,%7},{%8,%9},{%0,%1,%2,%3};"
        :"+f"(d[0]),"+f"(d[1]),"+f"(d[2]),"+f"(d[3])
        :"r"(a[0]),"r"(a[1]),"r"(a[2]),"r"(a[3]),"r"(b0),"r"(b1));
}
static __device__ __forceinline__ uint32_t packh(float a, float b){
    __half2 t; t.x=__float2half_rn(a); t.y=__float2half_rn(b);
    return *(uint32_t*)&t;
}
// stage a 64-row fp16 tile (Q / pass-1 K)
static __device__ __forceinline__ void stage64(uint32_t dst, const __half* src, int kk0, int tid){
#pragma unroll
    for(int i=0;i<4;i++){
        int idx=tid+i*128, row=idx>>3, seg=idx&7;
        CP16(dst+row*144+seg*16, src+(size_t)(kk0+row)*DH+seg*8);
    }
}
// stage a 32-row fp16 tile
static __device__ __forceinline__ void stage32(uint32_t dst, const __half* src, int kk0, int tid){
#pragma unroll
    for(int i=0;i<2;i++){
        int idx=tid+i*128, row=idx>>3, seg=idx&7;
        CP16(dst+row*144+seg*16, src+(size_t)(kk0+row)*DH+seg*8);
    }
}
static __device__ __forceinline__ void stage2(uint32_t dst, const __half* kh, const __half* vh, int kk0, int tid){
    stage32(dst,        kh, kk0, tid);
    stage32(dst+TILE_B, vh, kk0, tid);
}

static __device__ __forceinline__ void hi_store(__half* hi, int i, float4 x, float sc){
    x.x*=sc; x.y*=sc; x.z*=sc; x.w*=sc;
    __half2 a{__float2half_rn(x.x),__float2half_rn(x.y)};
    __half2 b{__float2half_rn(x.z),__float2half_rn(x.w)};
    ((uint2*)hi)[i] = make_uint2(*(uint32_t*)&a, *(uint32_t*)&b);
}
__global__ void preconv_kernel(const float4* __restrict__ q, const float4* __restrict__ k, const float4* __restrict__ v){
    int i = blockIdx.x*blockDim.x + threadIdx.x;   // NELEM/4 threads
    hi_store(g_qhi, i, q[i], 0.125f);
    hi_store(g_khi, i, k[i], 1.0f);
    hi_store(g_vhi, i, v[i], 1.0f);
}

__global__ void __launch_bounds__(128,4)
attn_mma_kernel(const int* __restrict__ gmask, float* __restrict__ gout, float* __restrict__ gattn)
{
    extern __shared__ __align__(16) char smem[];
    const uint32_t sb = smem_u32(smem);
    const int tid=threadIdx.x, lane=tid&31, w=tid>>5;
    const int gid=lane>>2, tig=lane&3;
    const int bh=blockIdx.y, b=bh>>4, q0=blockIdx.x*MTILE;

    const __half* khi_g = g_khi + (size_t)bh*NSEQ*DH;
    const __half* vhi_g = g_vhi + (size_t)bh*NSEQ*DH;

    // stage Q into permanent region
    stage64(sb+SM_QHI, g_qhi + ((size_t)bh*NSEQ+q0)*DH, 0, tid);
    CP_COMMIT();
    // pass-1 chunk 0: 64-row Khi tile
    stage64(sb+SM_BUF, khi_g, 0, tid); CP_COMMIT();
    CP_WAIT1();              // Q staging complete
    __syncthreads();

    const int lrow=(lane&7)+((lane>>3)&1)*8, lcol=(lane>>4)*16;
    // Q A-fragments resident
    uint32_t qhiF[4][4];
#pragma unroll
    for(int ks=0;ks<4;ks++){
        uint32_t a = sb+SM_QHI+(uint32_t)(w*16+lrow)*144+ks*32+lcol;
        LDSM4(qhiF[ks][0],qhiF[ks][1],qhiF[ks][2],qhiF[ks][3],a);
    }

    const int mq0 = __ldg(gmask + b*NSEQ+q0+w*16+gid);
    const int mq1 = __ldg(gmask + b*NSEQ+q0+w*16+gid+8);
    const int* mrow = gmask + b*NSEQ;
    const int rB=((lane>>4)&1)*8+(lane&7), cB=((lane>>3)&1)*16;   // K B-frag addressing
    const int rV=((lane>>3)&1)*8+(lane&7), cV=(lane>>4)*16;       // V B-frag (trans) addressing

    // ---------------- PASS 1: row sums (hi-only QK, 64-row chunks) ----------------
    float l0=0.f, l1=0.f;
    for(int c=0;c<NP1CHUNK;c++){
        if(c+1<NP1CHUNK) stage64(sb+SM_BUF+((c+1)&1)*BUF_B, khi_g, (c+1)*P1CHUNK, tid);
        CP_COMMIT(); CP_WAIT1(); __syncthreads();
        const uint32_t kb = sb+SM_BUF+(c&1)*BUF_B;
        float s[8][4];
#pragma unroll
        for(int nt=0;nt<8;nt++){ s[nt][0]=0.f;s[nt][1]=0.f;s[nt][2]=0.f;s[nt][3]=0.f; }
#pragma unroll
        for(int np=0;np<4;np++)
#pragma unroll
        for(int ks=0;ks<4;ks++){
            uint32_t b0,b1,b2,b3;
            LDSM4(b0,b1,b2,b3, kb+(uint32_t)(16*np+rB)*144+ks*32+cB);
            mma_f16(s[2*np],   qhiF[ks], b0,b1);
            mma_f16(s[2*np+1], qhiF[ks], b2,b3);
        }
        const int c0=c*P1CHUNK;
#pragma unroll
        for(int nt=0;nt<8;nt++){
            int2 mk = __ldg((const int2*)(mrow + c0+8*nt+2*tig));
            float e0 = mq0?1.f:(mk.x?0.f:__expf(s[nt][0]));
            float e1 = mq0?1.f:(mk.y?0.f:__expf(s[nt][1]));
            float e2 = mq1?1.f:(mk.x?0.f:__expf(s[nt][2]));
            float e3 = mq1?1.f:(mk.y?0.f:__expf(s[nt][3]));
            l0 += e0+e1; l1 += e2+e3;
        }
        __syncthreads();
    }
    l0 += __shfl_xor_sync(~0u,l0,1); l0 += __shfl_xor_sync(~0u,l0,2);
    l1 += __shfl_xor_sync(~0u,l1,1); l1 += __shfl_xor_sync(~0u,l1,2);
    const float inv0=1.f/l0, inv1=1.f/l1;

    // ---------------- PASS 2: hi-only QK -> normalized p -> attn store + 1-split PV ----------------
    float o[8][4];
#pragma unroll
    for(int nt=0;nt<8;nt++){ o[nt][0]=0.f;o[nt][1]=0.f;o[nt][2]=0.f;o[nt][3]=0.f; }
    float* arow0 = gattn + ((size_t)bh*NSEQ+q0+w*16+gid)*NSEQ;
    float* arow1 = arow0 + (size_t)8*NSEQ;

    stage2(sb+SM_BUF, khi_g,vhi_g, 0, tid); CP_COMMIT();
    for(int c=0;c<NCHUNK;c++){
        if(c+1<NCHUNK) stage2(sb+SM_BUF+((c+1)&1)*BUF_B, khi_g,vhi_g, (c+1)*CHUNK, tid);
        CP_COMMIT(); CP_WAIT1(); __syncthreads();
        const uint32_t bb = sb+SM_BUF+(c&1)*BUF_B;

        // QK hi-only (identical S to pass 1 -> l normalizes exactly)
        float s[4][4];
#pragma unroll
        for(int nt=0;nt<4;nt++){ s[nt][0]=0.f;s[nt][1]=0.f;s[nt][2]=0.f;s[nt][3]=0.f; }
#pragma unroll
        for(int np=0;np<2;np++)
#pragma unroll
        for(int ks=0;ks<4;ks++){
            uint32_t h0,h1,h2,h3;
            uint32_t off = (uint32_t)(16*np+rB)*144+ks*32+cB;
            LDSM4(h0,h1,h2,h3, bb+off);
            mma_f16(s[2*np],   qhiF[ks], h0,h1); mma_f16(s[2*np+1], qhiF[ks], h2,h3);
        }
        // epilogue: p = e*inv (normalized), store p fp32, pack p as fp16 PV A-frags
        uint32_t pa[2][4];
        const int c0=c*CHUNK;
#pragma unroll
        for(int nt=0;nt<4;nt++){
            int2 mk = __ldg((const int2*)(mrow + c0+8*nt+2*tig));
            float p0 = (mq0?1.f:(mk.x?0.f:__expf(s[nt][0])))*inv0;
            float p1 = (mq0?1.f:(mk.y?0.f:__expf(s[nt][1])))*inv0;
            float p2 = (mq1?1.f:(mk.x?0.f:__expf(s[nt][2])))*inv1;
            float p3 = (mq1?1.f:(mk.y?0.f:__expf(s[nt][3])))*inv1;
            *(float2*)(arow0 + c0+8*nt+2*tig) = make_float2(p0,p1);
            *(float2*)(arow1 + c0+8*nt+2*tig) = make_float2(p2,p3);
            pa[nt>>1][(nt&1)*2+0] = packh(p0,p1);
            pa[nt>>1][(nt&1)*2+1] = packh(p2,p3);
        }
        // PV 1-split (p*vhi; V via ldmatrix.trans)
#pragma unroll
        for(int np=0;np<4;np++)
#pragma unroll
        for(int ks=0;ks<2;ks++){
            uint32_t h0,h1,h2,h3;
            uint32_t off = (uint32_t)(16*ks+rV)*144+np*32+cV;
            LDSM4T(h0,h1,h2,h3, bb+TILE_B+off);
            mma_f16(o[2*np],   pa[ks], h0,h1); mma_f16(o[2*np+1], pa[ks], h2,h3);
        }
        __syncthreads();
    }

    // store O (already normalized)
    float* orow0 = gout + ((size_t)bh*NSEQ+q0+w*16+gid)*DH;
    float* orow1 = orow0 + 8*DH;
#pragma unroll
    for(int nt=0;nt<8;nt++){
        *(float2*)(orow0 + 8*nt+2*tig) = make_float2(o[nt][0],o[nt][1]);
        *(float2*)(orow1 + 8*nt+2*tig) = make_float2(o[nt][2],o[nt][3]);
    }
}

extern "C" void kernel_launch(void* const* d_in, const int* in_sizes, int n_in,
                              void* d_out, int out_size)
{
    const float* q=(const float*)d_in[0];
    const float* k=(const float*)d_in[1];
    const float* v=(const float*)d_in[2];
    const int* mask=(const int*)d_in[3];
    float* out=(float*)d_out;
    float* attn=out + (size_t)NBH*NSEQ*DH;

    preconv_kernel<<<NELEM/4/256, 256>>>((const float4*)q,(const float4*)k,(const float4*)v);

    static_assert(SMEM_TOTAL <= 58112, "smem");
    cudaFuncSetAttribute(attn_mma_kernel, cudaFuncAttributeMaxDynamicSharedMemorySize, SMEM_TOTAL);
    attn_mma_kernel<<<dim3(NSEQ/MTILE, NBH), 128, SMEM_TOTAL>>>(mask, out, attn);
}

// round 16
// speedup vs baseline: 1.1077x; 1.1077x over previous
#include <cuda_runtime.h>
#include <cuda_fp16.h>
#include <cstdint>

#define NSEQ 2048
#define DH 64
#define NBH 32
#define MTILE 64
#define CHUNK 32
#define NCHUNK (NSEQ/CHUNK)     // 64  (pass 2)
#define P1CHUNK 64
#define NP1CHUNK (NSEQ/P1CHUNK) // 32  (pass 1)
#define NELEM (NBH*NSEQ*DH)     // 4194304

// preconverted fp16 operands (q pre-scaled by 1/8, split hi/lo; k,v hi only)
__device__ __align__(16) __half g_qhi[NELEM], g_qlo[NELEM];
__device__ __align__(16) __half g_khi[NELEM];
__device__ __align__(16) __half g_vhi[NELEM];

// smem layout (144B row stride):
//   Qhi (64 rows, 9216B) | Qlo (9216B) | 2 x 9216B buffers
//   pass 1: each buffer = one 64-row Khi tile
//   pass 2: each buffer = [Khi|Vhi] 32-row tiles
#define SM_QHI 0
#define SM_QLO 9216
#define SM_BUF 18432
#define TILE_B (CHUNK*144)      // 4608
#define BUF_B  (2*TILE_B)       // 9216
#define SMEM_TOTAL (SM_BUF + 2*BUF_B)   // 36864 -> 4 CTAs/SM (reg-capped)

#define CP16(d,s)   asm volatile("cp.async.cg.shared.global [%0], [%1], 16;"::"r"(d),"l"(s))
#define CP_COMMIT() asm volatile("cp.async.commit_group;")
#define CP_WAIT0()  asm volatile("cp.async.wait_group 0;")
#define CP_WAIT1()  asm volatile("cp.async.wait_group 1;")
#define LDSM4(r0,r1,r2,r3,a)  asm volatile("ldmatrix.sync.aligned.m8n8.x4.shared.b16 {%0,%1,%2,%3},[%4];":"=r"(r0),"=r"(r1),"=r"(r2),"=r"(r3):"r"(a))
#define LDSM4T(r0,r1,r2,r3,a) asm volatile("ldmatrix.sync.aligned.m8n8.x4.trans.shared.b16 {%0,%1,%2,%3},[%4];":"=r"(r0),"=r"(r1),"=r"(r2),"=r"(r3):"r"(a))

static __device__ __forceinline__ uint32_t smem_u32(const void* p){
    uint32_t a; asm("{ .reg .u64 t; cvta.to.shared.u64 t, %1; cvt.u32.u64 %0, t; }":"=r"(a):"l"(p)); return a;
}
static __device__ __forceinline__ void mma_f16(float* d, const uint32_t* a, uint32_t b0, uint32_t b1){
    asm volatile("mma.sync.aligned.m16n8k16.row.col.f32.f16.f16.f32 "
        "{%0,%1,%2,%3},{%4,%5,%6,%7},{%8,%9},{%0,%1,%2,%3};"
        :"+f"(d[0]),"+f"(d[1]),"+f"(d[2]),"+f"(d[3])
        :"r"(a[0]),"r"(a[1]),"r"(a[2]),"r"(a[3]),"r"(b0),"r"(b1));
}
static __device__ __forceinline__ uint32_t packh(float a, float b){
    __half2 t; t.x=__float2half_rn(a); t.y=__float2half_rn(b);
    return *(uint32_t*)&t;
}
// stage a 64-row fp16 tile (Q / pass-1 K)
static __device__ __forceinline__ void stage64(uint32_t dst, const __half* src, int kk0, int tid){
#pragma unroll
    for(int i=0;i<4;i++){
        int idx=tid+i*128, row=idx>>3, seg=idx&7;
        CP16(dst+row*144+seg*16, src+(size_t)(kk0+row)*DH+seg*8);
    }
}
// stage a 32-row fp16 tile
static __device__ __forceinline__ void stage32(uint32_t dst, const __half* src, int kk0, int tid){
#pragma unroll
    for(int i=0;i<2;i++){
        int idx=tid+i*128, row=idx>>3, seg=idx&7;
        CP16(dst+row*144+seg*16, src+(size_t)(kk0+row)*DH+seg*8);
    }
}
static __device__ __forceinline__ void stage2(uint32_t dst, const __half* kh, const __half* vh, int kk0, int tid){
    stage32(dst,        kh, kk0, tid);
    stage32(dst+TILE_B, vh, kk0, tid);
}

static __device__ __forceinline__ void split_store(__half* hi, __half* lo, int i, float4 x, float sc){
    x.x*=sc; x.y*=sc; x.z*=sc; x.w*=sc;
    __half h0=__float2half_rn(x.x), h1=__float2half_rn(x.y);
    __half h2=__float2half_rn(x.z), h3=__float2half_rn(x.w);
    __half l0=__float2half_rn(x.x-__half2float(h0));
    __half l1=__float2half_rn(x.y-__half2float(h1));
    __half l2=__float2half_rn(x.z-__half2float(h2));
    __half l3=__float2half_rn(x.w-__half2float(h3));
    __half2 a{h0,h1}, b{h2,h3}, c{l0,l1}, d{l2,l3};
    ((uint2*)hi)[i] = make_uint2(*(uint32_t*)&a, *(uint32_t*)&b);
    ((uint2*)lo)[i] = make_uint2(*(uint32_t*)&c, *(uint32_t*)&d);
}
static __device__ __forceinline__ void hi_store(__half* hi, int i, float4 x){
    __half2 a{__float2half_rn(x.x),__float2half_rn(x.y)};
    __half2 b{__float2half_rn(x.z),__float2half_rn(x.w)};
    ((uint2*)hi)[i] = make_uint2(*(uint32_t*)&a, *(uint32_t*)&b);
}
__global__ void preconv_kernel(const float4* __restrict__ q, const float4* __restrict__ k, const float4* __restrict__ v){
    int i = blockIdx.x*blockDim.x + threadIdx.x;   // NELEM/4 threads
    split_store(g_qhi, g_qlo, i, q[i], 0.125f);
    hi_store(g_khi, i, k[i]);
    hi_store(g_vhi, i, v[i]);
}

__global__ void __launch_bounds__(128,4)
attn_mma_kernel(const int* __restrict__ gmask, float* __restrict__ gout, float* __restrict__ gattn)
{
    extern __shared__ __align__(16) char smem[];
    const uint32_t sb = smem_u32(smem);
    const int tid=threadIdx.x, lane=tid&31, w=tid>>5;
    const int gid=lane>>2, tig=lane&3;
    const int bh=blockIdx.y, b=bh>>4, q0=blockIdx.x*MTILE;

    const __half* khi_g = g_khi + (size_t)bh*NSEQ*DH;
    const __half* vhi_g = g_vhi + (size_t)bh*NSEQ*DH;

    // stage Q hi/lo into permanent region
    stage64(sb+SM_QHI, g_qhi + ((size_t)bh*NSEQ+q0)*DH, 0, tid);
    stage64(sb+SM_QLO, g_qlo + ((size_t)bh*NSEQ+q0)*DH, 0, tid);
    CP_COMMIT();
    // pass-1 chunk 0: 64-row Khi tile
    stage64(sb+SM_BUF, khi_g, 0, tid); CP_COMMIT();
    CP_WAIT1();              // Q staging complete (chunk0 may be in flight)
    __syncthreads();

    const int lrow=(lane&7)+((lane>>3)&1)*8, lcol=(lane>>4)*16;
    // Q-hi A-fragments resident; Q-lo reloaded per pass-2 chunk
    uint32_t qhiF[4][4];
#pragma unroll
    for(int ks=0;ks<4;ks++){
        uint32_t a = sb+SM_QHI+(uint32_t)(w*16+lrow)*144+ks*32+lcol;
        LDSM4(qhiF[ks][0],qhiF[ks][1],qhiF[ks][2],qhiF[ks][3],a);
    }

    const int mq0 = __ldg(gmask + b*NSEQ+q0+w*16+gid);
    const int mq1 = __ldg(gmask + b*NSEQ+q0+w*16+gid+8);
    const int* mrow = gmask + b*NSEQ;
    const int rB=((lane>>4)&1)*8+(lane&7), cB=((lane>>3)&1)*16;   // K B-frag addressing
    const int rV=((lane>>3)&1)*8+(lane&7), cV=(lane>>4)*16;       // V B-frag (trans) addressing

    // ---------------- PASS 1: row sums (hi-only QK, 64-row chunks) ----------------
    // single-sync double buffer: wait(cur) -> sync -> stage(next) -> compute(cur)
    float l0=0.f, l1=0.f;
    for(int c=0;c<NP1CHUNK;c++){
        CP_WAIT0(); __syncthreads();
        if(c+1<NP1CHUNK){ stage64(sb+SM_BUF+((c+1)&1)*BUF_B, khi_g, (c+1)*P1CHUNK, tid); CP_COMMIT(); }
        const uint32_t kb = sb+SM_BUF+(c&1)*BUF_B;
        float s[8][4];
#pragma unroll
        for(int nt=0;nt<8;nt++){ s[nt][0]=0.f;s[nt][1]=0.f;s[nt][2]=0.f;s[nt][3]=0.f; }
#pragma unroll
        for(int np=0;np<4;np++)
#pragma unroll
        for(int ks=0;ks<4;ks++){
            uint32_t b0,b1,b2,b3;
            LDSM4(b0,b1,b2,b3, kb+(uint32_t)(16*np+rB)*144+ks*32+cB);
            mma_f16(s[2*np],   qhiF[ks], b0,b1);
            mma_f16(s[2*np+1], qhiF[ks], b2,b3);
        }
        const int c0=c*P1CHUNK;
#pragma unroll
        for(int nt=0;nt<8;nt++){
            int2 mk = __ldg((const int2*)(mrow + c0+8*nt+2*tig));
            float e0 = mq0?1.f:(mk.x?0.f:__expf(s[nt][0]));
            float e1 = mq0?1.f:(mk.y?0.f:__expf(s[nt][1]));
            float e2 = mq1?1.f:(mk.x?0.f:__expf(s[nt][2]));
            float e3 = mq1?1.f:(mk.y?0.f:__expf(s[nt][3]));
            l0 += e0+e1; l1 += e2+e3;
        }
    }
    l0 += __shfl_xor_sync(~0u,l0,1); l0 += __shfl_xor_sync(~0u,l0,2);
    l1 += __shfl_xor_sync(~0u,l1,1); l1 += __shfl_xor_sync(~0u,l1,2);
    const float inv0=1.f/l0, inv1=1.f/l1;

    // ---------------- PASS 2: 2-split QK -> normalized p -> attn store + 1-split PV ----------------
    float o[8][4];
#pragma unroll
    for(int nt=0;nt<8;nt++){ o[nt][0]=0.f;o[nt][1]=0.f;o[nt][2]=0.f;o[nt][3]=0.f; }
    float* arow0 = gattn + ((size_t)bh*NSEQ+q0+w*16+gid)*NSEQ;
    float* arow1 = arow0 + (size_t)8*NSEQ;

    // stage pass-2 chunk 0 into buffer 0 (buffer 0 last read at pass-1 c=30;
    // every warp passed the c=31 top-sync, so all reads are complete)
    stage2(sb+SM_BUF, khi_g,vhi_g, 0, tid); CP_COMMIT();
    for(int c=0;c<NCHUNK;c++){
        CP_WAIT0(); __syncthreads();
        if(c+1<NCHUNK){ stage2(sb+SM_BUF+((c+1)&1)*BUF_B, khi_g,vhi_g, (c+1)*CHUNK, tid); CP_COMMIT(); }
        const uint32_t bb = sb+SM_BUF+(c&1)*BUF_B;

        // Q-lo frags from the immutable Q region
        uint32_t qloF[4][4];
#pragma unroll
        for(int ks=0;ks<4;ks++){
            uint32_t a = sb+SM_QLO+(uint32_t)(w*16+lrow)*144+ks*32+lcol;
            LDSM4(qloF[ks][0],qloF[ks][1],qloF[ks][2],qloF[ks][3],a);
        }

        // QK 2-split (q_hi*k_hi + q_lo*k_hi)
        float s[4][4];
#pragma unroll
        for(int nt=0;nt<4;nt++){ s[nt][0]=0.f;s[nt][1]=0.f;s[nt][2]=0.f;s[nt][3]=0.f; }
#pragma unroll
        for(int np=0;np<2;np++)
#pragma unroll
        for(int ks=0;ks<4;ks++){
            uint32_t h0,h1,h2,h3;
            uint32_t off = (uint32_t)(16*np+rB)*144+ks*32+cB;
            LDSM4(h0,h1,h2,h3, bb+off);
            mma_f16(s[2*np],   qhiF[ks], h0,h1); mma_f16(s[2*np+1], qhiF[ks], h2,h3);
            mma_f16(s[2*np],   qloF[ks], h0,h1); mma_f16(s[2*np+1], qloF[ks], h2,h3);
        }
        // epilogue: p = e*inv (normalized), store p fp32, pack p as fp16 PV A-frags
        uint32_t pa[2][4];
        const int c0=c*CHUNK;
#pragma unroll
        for(int nt=0;nt<4;nt++){
            int2 mk = __ldg((const int2*)(mrow + c0+8*nt+2*tig));
            float p0 = (mq0?1.f:(mk.x?0.f:__expf(s[nt][0])))*inv0;
            float p1 = (mq0?1.f:(mk.y?0.f:__expf(s[nt][1])))*inv0;
            float p2 = (mq1?1.f:(mk.x?0.f:__expf(s[nt][2])))*inv1;
            float p3 = (mq1?1.f:(mk.y?0.f:__expf(s[nt][3])))*inv1;
            *(float2*)(arow0 + c0+8*nt+2*tig) = make_float2(p0,p1);
            *(float2*)(arow1 + c0+8*nt+2*tig) = make_float2(p2,p3);
            pa[nt>>1][(nt&1)*2+0] = packh(p0,p1);
            pa[nt>>1][(nt&1)*2+1] = packh(p2,p3);
        }
        // PV 1-split (p*vhi; V via ldmatrix.trans)
#pragma unroll
        for(int np=0;np<4;np++)
#pragma unroll
        for(int ks=0;ks<2;ks++){
            uint32_t h0,h1,h2,h3;
            uint32_t off = (uint32_t)(16*ks+rV)*144+np*32+cV;
            LDSM4T(h0,h1,h2,h3, bb+TILE_B+off);
            mma_f16(o[2*np],   pa[ks], h0,h1); mma_f16(o[2*np+1], pa[ks], h2,h3);
        }
    }

    // store O (already normalized)
    float* orow0 = gout + ((size_t)bh*NSEQ+q0+w*16+gid)*DH;
    float* orow1 = orow0 + 8*DH;
#pragma unroll
    for(int nt=0;nt<8;nt++){
        *(float2*)(orow0 + 8*nt+2*tig) = make_float2(o[nt][0],o[nt][1]);
        *(float2*)(orow1 + 8*nt+2*tig) = make_float2(o[nt][2],o[nt][3]);
    }
}

extern "C" void kernel_launch(void* const* d_in, const int* in_sizes, int n_in,
                              void* d_out, int out_size)
{
    const float* q=(const float*)d_in[0];
    const float* k=(const float*)d_in[1];
    const float* v=(const float*)d_in[2];
    const int* mask=(const int*)d_in[3];
    float* out=(float*)d_out;
    float* attn=out + (size_t)NBH*NSEQ*DH;

    preconv_kernel<<<NELEM/4/256, 256>>>((const float4*)q,(const float4*)k,(const float4*)v);

    static_assert(SMEM_TOTAL <= 58112, "smem");
    cudaFuncSetAttribute(attn_mma_kernel, cudaFuncAttributeMaxDynamicSharedMemorySize, SMEM_TOTAL);
    attn_mma_kernel<<<dim3(NSEQ/MTILE, NBH), 128, SMEM_TOTAL>>>(mask, out, attn);
}